// round 17
// baseline (speedup 1.0000x reference)
#include <cuda_runtime.h>
#include <cstdint>
#include <cstddef>

#define BB 64
#define TT 512
#define II 128
#define HH 512
#define NCLS 5

typedef unsigned long long u64;
typedef ulonglong2 ull2;

// Scratch — static __device__ arrays per allocation rules.
__device__ float g_xp0[(size_t)BB * TT * HH];   // layer0 xproj
__device__ float g_xp1[(size_t)BB * TT * HH];   // layer1 xproj
__device__ float g_xp2[(size_t)BB * TT * HH];   // layer2 xproj
__device__ float g_ys0[(size_t)BB * TT * HH];   // layer0 hidden
__device__ float g_ys1[(size_t)BB * TT * HH];   // layer1 hidden
__device__ float g_ys2[(size_t)BB * TT * HH];   // layer2 hidden (only t=511 used)

// Cross-CTA coordination (reset before each mega launch).
__device__ int g_jcA;        // A-phase job queue head
__device__ int g_jcB;        // B-phase job queue head
__device__ int g_dA[4];      // A jobs completed per t-block
__device__ int g_dB[4];      // B jobs completed per t-block
__device__ int g_prog[64];   // recurrence progress per (cluster, rank)

// ---------------- packed f32x2 helpers ----------------
__device__ __forceinline__ u64 pk2(float x, float y) {
    u64 r; asm("mov.b64 %0, {%1,%2};" : "=l"(r) : "f"(x), "f"(y)); return r;
}
__device__ __forceinline__ float2 upk2(u64 v) {
    float2 f; asm("mov.b64 {%0,%1}, %2;" : "=f"(f.x), "=f"(f.y) : "l"(v)); return f;
}
__device__ __forceinline__ void fma2(u64 &d, u64 a, u64 b) {
    asm("fma.rn.f32x2 %0, %1, %2, %0;" : "+l"(d) : "l"(a), "l"(b));
}

// ---------------- cluster / mbarrier helpers ----------------
__device__ __forceinline__ uint32_t smem_u32(const void* p) {
    uint32_t a;
    asm("{ .reg .u64 t; cvta.to.shared.u64 t, %1; cvt.u32.u64 %0, t; }"
        : "=r"(a) : "l"(p));
    return a;
}
__device__ __forceinline__ uint32_t mapa_u32(uint32_t local, uint32_t rank) {
    uint32_t r;
    asm("mapa.shared::cluster.u32 %0, %1, %2;" : "=r"(r) : "r"(local), "r"(rank));
    return r;
}
__device__ __forceinline__ void mbar_init(uint32_t addr, uint32_t count) {
    asm volatile("mbarrier.init.shared.b64 [%0], %1;" :: "r"(addr), "r"(count) : "memory");
}
__device__ __forceinline__ void mbar_expect_tx(uint32_t addr, uint32_t bytes) {
    asm volatile("mbarrier.arrive.expect_tx.shared.b64 _, [%0], %1;"
                 :: "r"(addr), "r"(bytes) : "memory");
}
__device__ __forceinline__ void bulk_copy_cluster(uint32_t dst_cluster, uint32_t src_cta,
                                                  uint32_t bytes, uint32_t mbar_cluster) {
    asm volatile("cp.async.bulk.shared::cluster.shared::cta.mbarrier::complete_tx::bytes "
                 "[%0], [%1], %2, [%3];"
                 :: "r"(dst_cluster), "r"(src_cta), "r"(bytes), "r"(mbar_cluster) : "memory");
}
__device__ __forceinline__ void mbar_wait_cluster(uint32_t addr, uint32_t parity) {
    asm volatile(
        "{\n\t"
        ".reg .pred P;\n\t"
        "WLP%=:\n\t"
        "mbarrier.try_wait.parity.acquire.cluster.shared::cta.b64 P, [%0], %1, 0x989680;\n\t"
        "@P bra WDN%=;\n\t"
        "bra WLP%=;\n\t"
        "WDN%=:\n\t"
        "}"
        :: "r"(addr), "r"(parity) : "memory");
}
__device__ __forceinline__ void fence_proxy_async_cta() {
    asm volatile("fence.proxy.async.shared::cta;" ::: "memory");
}
__device__ __forceinline__ void cluster_sync_full() {
    asm volatile("barrier.cluster.arrive.aligned;" ::: "memory");
    asm volatile("barrier.cluster.wait.aligned;" ::: "memory");
}

// =======================================================================
// One 128x128 GEMM tile: C = A[0:128,0:K] @ W[0:128,0:K]^T + b1 + b2.
// =======================================================================
__device__ __forceinline__ void gemm_tile(
    const float* __restrict__ A, const float* __restrict__ W,
    const float* __restrict__ b1, const float* __restrict__ b2,
    float* __restrict__ C, int K,
    u64 (*As2)[128], u64 (*Bs2)[128])
{
    const int tid = threadIdx.x;
    const int tx = tid & 15;
    const int ty = tid >> 4;
    const int r0  = tid >> 2;
    const int kq0 = tid & 3;

    u64 acc[8][8];
    #pragma unroll
    for (int i = 0; i < 8; i++)
        #pragma unroll
        for (int j = 0; j < 8; j++) acc[i][j] = 0ull;

    const float* pa0 = &A[(size_t)r0        * K + kq0 * 4];
    const float* pa1 = &A[(size_t)(64 + r0) * K + kq0 * 4];
    const float* pw0 = &W[(size_t)r0        * K + kq0 * 4];
    const float* pw1 = &W[(size_t)(64 + r0) * K + kq0 * 4];

    const int ktiles = K >> 4;
    float4 a0 = *(const float4*)pa0;
    float4 a1 = *(const float4*)pa1;
    float4 w0 = *(const float4*)pw0;
    float4 w1 = *(const float4*)pw1;

    for (int kt = 0; kt < ktiles; kt++) {
        __syncthreads();
        As2[kq0 * 2][r0]          = pk2(a0.x, a0.y);
        As2[kq0 * 2 + 1][r0]      = pk2(a0.z, a0.w);
        As2[kq0 * 2][64 + r0]     = pk2(a1.x, a1.y);
        As2[kq0 * 2 + 1][64 + r0] = pk2(a1.z, a1.w);
        Bs2[kq0 * 2][r0]          = pk2(w0.x, w0.y);
        Bs2[kq0 * 2 + 1][r0]      = pk2(w0.z, w0.w);
        Bs2[kq0 * 2][64 + r0]     = pk2(w1.x, w1.y);
        Bs2[kq0 * 2 + 1][64 + r0] = pk2(w1.z, w1.w);
        __syncthreads();

        if (kt + 1 < ktiles) {
            const int kb = (kt + 1) * 16;
            a0 = *(const float4*)(pa0 + kb);
            a1 = *(const float4*)(pa1 + kb);
            w0 = *(const float4*)(pw0 + kb);
            w1 = *(const float4*)(pw1 + kb);
        }

        #pragma unroll
        for (int k2 = 0; k2 < 8; k2++) {
            u64 af[8], bf[8];
            #pragma unroll
            for (int i = 0; i < 8; i++) af[i] = As2[k2][ty + 16 * i];
            #pragma unroll
            for (int j = 0; j < 8; j++) bf[j] = Bs2[k2][tx + 16 * j];
            #pragma unroll
            for (int i = 0; i < 8; i++)
                #pragma unroll
                for (int j = 0; j < 8; j++)
                    fma2(acc[i][j], af[i], bf[j]);
        }
    }

    float bias8[8];
    #pragma unroll
    for (int j = 0; j < 8; j++) {
        int n = tx + 16 * j;
        bias8[j] = b1[n] + b2[n];
    }
    #pragma unroll
    for (int i = 0; i < 8; i++) {
        const size_t m = (size_t)(ty + 16 * i);
        #pragma unroll
        for (int j = 0; j < 8; j++) {
            float2 p = upk2(acc[i][j]);
            C[m * HH + tx + 16 * j] = p.x + p.y + bias8[j];
        }
    }
}

// ---- one B job: fine-gate on g_prog, gemm, count. NOINLINE so callers'
// register-resident state spills only around actual calls. ----
__device__ __noinline__ void do_B_job(
    int j, const float* ysrc, const float* Wn,
    const float* b1, const float* b2, float* Cdst,
    u64 (*As2)[128], u64 (*Bs2)[128])
{
    const int tb = j >> 8, r8 = j & 255, b = r8 >> 2, nt = r8 & 3;
    if (threadIdx.x == 0) {
        volatile int* p = (volatile int*)&g_prog[(b >> 3) * 8];
        const int thr = tb * 128 + 128;
        for (int q = 0; q < 8; q++)
            while (p[q] < thr) __nanosleep(128);
        __threadfence();
    }
    __syncthreads();
    gemm_tile(ysrc + (size_t)(b * TT + tb * 128) * HH,
              Wn + (size_t)(nt * 128) * HH,
              b1 + nt * 128, b2 + nt * 128,
              Cdst + (size_t)(b * TT + tb * 128) * HH + nt * 128,
              HH, As2, Bs2);
    __syncthreads();
    __threadfence();
    if (threadIdx.x == 0) atomicAdd(&g_dB[tb], 1);
    __syncthreads();
}

// ---- blocking worker: claims jobs until queue drains ----
__device__ void worker_loop(
    const float* ysrc, const float* Wn, const float* b1, const float* b2,
    float* Cdst, u64 (*As2)[128], u64 (*Bs2)[128], int* s_job)
{
    for (;;) {
        if (threadIdx.x == 0) *s_job = atomicAdd(&g_jcB, 1);
        __syncthreads();
        const int j = *s_job;
        __syncthreads();
        if (j >= 1024) break;
        do_B_job(j, ysrc, Wn, b1, b2, Cdst, As2, Bs2);
    }
}

// =======================================================================
// Recurrence (R9-exact): 8-CTA cluster, 8 batches as 2 groups of 4,
// per-(group,buf,chunk) mbarriers, 16 x 1KB bulk-engine pushes per step.
// GATE: 0 = none, 1 = wait g_dA blocks, 2 = wait g_dB blocks and HELP the
// B queue while blocked (CAS-claim only verified-open head jobs).
// =======================================================================
template<int GATE, bool PUBLISH, bool YSALL>
__device__ void rnn_run(
    const float* __restrict__ xp, const float* __restrict__ Whh,
    float* __restrict__ ys, int bg, int r, int prog_idx,
    ull2 (*h_s)[2][8][4][16], float (*redv)[4][64],
    float (*out_s)[2][4][64], u64 (*mbar)[2][8],
    // help context (GATE==2)
    const float* hsrc, const float* hW, const float* hb1, const float* hb2,
    float* hC, u64 (*As2)[128], u64 (*Bs2)[128], int* s_help)
{
    const int tid   = threadIdx.x;
    const int jbase = r * 64;
    const int jp = tid & 31;
    const int kc = tid >> 5;
    const int k0 = kc * 64;

    // W_hh slice in registers, k-pair packed
    u64 w[2][32];
    #pragma unroll
    for (int jj = 0; jj < 2; jj++) {
        const float* wrow = &Whh[(size_t)(jbase + jp + jj * 32) * HH + k0];
        #pragma unroll
        for (int kp = 0; kp < 32; kp++) {
            float2 wv = *(const float2*)&wrow[2 * kp];
            w[jj][kp] = pk2(wv.x, wv.y);
        }
    }

    {
        float4* hz = (float4*)h_s;
        for (int i = tid; i < 2 * 2 * 8 * 4 * 16; i += 256)
            hz[i] = make_float4(0.f, 0.f, 0.f, 0.f);
    }
    const uint32_t mb_base = smem_u32(&mbar[0][0][0]);
    const uint32_t hbase   = smem_u32(&h_s[0][0][0][0][0]);
    const uint32_t obase   = smem_u32(&out_s[0][0][0][0]);
    if (tid < 32) {
        mbar_init(mb_base + (uint32_t)tid * 8u, 1);
        mbar_expect_tx(mb_base + (uint32_t)tid * 8u, 1024u);
    }
    __syncthreads();
    cluster_sync_full();

    uint32_t my_mb[2][2];
    #pragma unroll
    for (int g = 0; g < 2; g++)
        #pragma unroll
        for (int b = 0; b < 2; b++)
            my_mb[g][b] = mb_base + (uint32_t)(((g * 2 + b) * 8 + kc)) * 8u;
    int par[2][2] = {{0, 0}, {0, 0}};

    uint32_t dst_q = 0;
    uint32_t rmb[2][2];
    if (tid < 8) {
        const uint32_t q = (uint32_t)tid;
        dst_q = mapa_u32(hbase, q) + (uint32_t)r * 1024u;
        #pragma unroll
        for (int g = 0; g < 2; g++)
            #pragma unroll
            for (int b = 0; b < 2; b++)
                rmb[g][b] = mapa_u32(mb_base + (uint32_t)(((g * 2 + b) * 8 + r)) * 8u, q);
    }

    const int cb = tid >> 6;
    const int cj = tid & 63;
    const float* xp_p[2];
    float*       ys_p[2];
    #pragma unroll
    for (int g = 0; g < 2; g++) {
        xp_p[g] = &xp[((size_t)(bg + g * 4 + cb) * TT) * HH + jbase + cj];
        ys_p[g] = &ys[((size_t)(bg + g * 4 + cb) * TT) * HH + jbase + cj];
    }

    for (int t = 0; t < TT; t++) {
        const int os   = t & 1;
        const int wbuf = os ^ 1;
        const bool push = (t + 1 < TT);

        // ---- xp availability gate every 128 steps ----
        if (GATE == 1 && (t & 127) == 0) {
            if (tid == 0) {
                while (((volatile int*)g_dA)[t >> 7] < 256)
                    __nanosleep(128);
                __threadfence();
            }
            __syncthreads();
        }
        if (GATE == 2 && (t & 127) == 0) {
            const int blk = t >> 7;
            for (;;) {
                if (tid == 0) {
                    int st = -2;
                    if (*(volatile int*)&g_dB[blk] >= 256) st = -1;
                    else {
                        const int h = *(volatile int*)&g_jcB;
                        if (h < 1024) {
                            const int hb = (h & 255) >> 2, htb = h >> 8;
                            volatile int* p = (volatile int*)&g_prog[(hb >> 3) * 8];
                            const int thr = htb * 128 + 128;
                            bool open = true;
                            for (int q = 0; q < 8; q++)
                                if (p[q] < thr) { open = false; break; }
                            // claim EXACTLY the verified-open head job
                            if (open && atomicCAS(&g_jcB, h, h + 1) == h)
                                st = h;
                        }
                    }
                    *s_help = st;
                }
                __syncthreads();
                const int st = *s_help;
                __syncthreads();
                if (st == -1) break;
                if (st >= 0)
                    do_B_job(st, hsrc, hW, hb1, hb2, hC, As2, Bs2);
                else if (tid == 0)
                    __nanosleep(512);
                __syncthreads();
            }
            if (tid == 0) __threadfence();
            __syncthreads();
        }

        float xpv[2];
        xpv[0] = __ldg(xp_p[0]);
        xpv[1] = __ldg(xp_p[1]);

        #pragma unroll
        for (int g = 0; g < 2; g++) {
            if (t > 0) {
                mbar_wait_cluster(my_mb[g][os], par[g][os]);
                if (jp == 0) mbar_expect_tx(my_mb[g][os], 1024u);
                par[g][os] ^= 1;
            }

            const ull2* hb = &h_s[g][os][kc][0][0];
            u64 acc0[4], acc1[4];
            #pragma unroll
            for (int b = 0; b < 4; b++) {
                u64 a0 = 0ull, a1 = 0ull;
                #pragma unroll
                for (int kv = 0; kv < 16; kv++) {
                    ull2 hv = hb[b * 16 + kv];
                    fma2(a0, w[0][2 * kv],     hv.x);
                    fma2(a0, w[0][2 * kv + 1], hv.y);
                    fma2(a1, w[1][2 * kv],     hv.x);
                    fma2(a1, w[1][2 * kv + 1], hv.y);
                }
                acc0[b] = a0; acc1[b] = a1;
            }

            #pragma unroll
            for (int b = 0; b < 4; b++) {
                float2 p0 = upk2(acc0[b]);
                float2 p1 = upk2(acc1[b]);
                redv[kc][b][jp]      = p0.x + p0.y;
                redv[kc][b][jp + 32] = p1.x + p1.y;
            }
            __syncthreads();

            {
                float s = xpv[g];
                #pragma unroll
                for (int c = 0; c < 8; c++) s += redv[c][cb][cj];
                s = fmaxf(s, 0.f);
                out_s[g][os][cb][cj] = s;
                if (YSALL || t == TT - 1)
                    *ys_p[g] = s;
                ys_p[g] += HH;
            }
            __syncthreads();

            if (push && tid < 8) {
                fence_proxy_async_cta();
                bulk_copy_cluster(dst_q + (uint32_t)g * 16384u + (uint32_t)wbuf * 8192u,
                                  obase + (uint32_t)(g * 2 + os) * 1024u,
                                  1024u, rmb[g][wbuf]);
            }
        }

        if (PUBLISH && (t & 31) == 31 && tid == 0) {
            __threadfence();
            ((volatile int*)g_prog)[prog_idx] = t + 1;
        }

        xp_p[0] += HH;
        xp_p[1] += HH;
    }

    cluster_sync_full();
}

// =======================================================================
// Launch 1 (R9-exact): A-phase (xp0 from x) drained by all; clusters 0..7
// rnn layer0 (gated on A, publishes prog); clusters 8..17 + finished rnn
// CTAs run the B queue (xp1 from ys0).
// =======================================================================
__global__ void __launch_bounds__(256, 1) __cluster_dims__(8, 1, 1)
megaL0(const float* __restrict__ x,
       const float* __restrict__ Wih0, const float* __restrict__ bi0,
       const float* __restrict__ bh0,
       const float* __restrict__ Whh0,
       const float* __restrict__ Wih1, const float* __restrict__ bi1,
       const float* __restrict__ bh1,
       float* __restrict__ xp0, float* __restrict__ xp1,
       float* __restrict__ ys0)
{
    __shared__ ull2 h_s[2][2][8][4][16];
    __shared__ float redv[8][4][64];
    __shared__ __align__(16) float out_s[2][2][4][64];
    __shared__ __align__(8) u64 mbar[2][2][8];
    __shared__ u64 As2[8][128];
    __shared__ u64 Bs2[8][128];
    __shared__ int s_job;

    const int tid = threadIdx.x;
    const int cl  = blockIdx.x >> 3;
    const int r   = blockIdx.x & 7;

    // phase A: everyone drains the layer-0 xproj queue
    for (;;) {
        if (tid == 0) s_job = atomicAdd(&g_jcA, 1);
        __syncthreads();
        const int j = s_job;
        __syncthreads();
        if (j >= 1024) break;
        const int tb = j >> 8, r8 = j & 255, b = r8 >> 2, nt = r8 & 3;
        gemm_tile(x + (size_t)(b * TT + tb * 128) * II,
                  Wih0 + (size_t)(nt * 128) * II,
                  bi0 + nt * 128, bh0 + nt * 128,
                  xp0 + (size_t)(b * TT + tb * 128) * HH + nt * 128,
                  II, As2, Bs2);
        __syncthreads();
        __threadfence();
        if (tid == 0) atomicAdd(&g_dA[tb], 1);
        __syncthreads();
    }

    if (cl >= 8) {
        worker_loop(ys0, Wih1, bi1, bh1, xp1, As2, Bs2, &s_job);
        return;
    }

    rnn_run<1, true, true>(xp0, Whh0, ys0, cl * 8, r, cl * 8 + r,
                           h_s, redv, out_s, mbar,
                           nullptr, nullptr, nullptr, nullptr, nullptr,
                           As2, Bs2, &s_job);

    worker_loop(ys0, Wih1, bi1, bh1, xp1, As2, Bs2, &s_job);
}

// =======================================================================
// Launch 2 (merged layers 1+2): clusters 0..7 rnn layer1 (publish prog,
// join B after); clusters 8..15 rnn layer2 (gated on g_dB, HELP while
// blocked); clusters 16..17 dedicated B workers (xp2 from ys1).
// =======================================================================
__global__ void __launch_bounds__(256, 1) __cluster_dims__(8, 1, 1)
megaL12(const float* __restrict__ xp1, const float* __restrict__ Whh1,
        float* __restrict__ ys1,
        const float* __restrict__ Wih2, const float* __restrict__ bi2,
        const float* __restrict__ bh2, float* __restrict__ xp2,
        const float* __restrict__ Whh2, float* __restrict__ ys2)
{
    __shared__ ull2 h_s[2][2][8][4][16];
    __shared__ float redv[8][4][64];
    __shared__ __align__(16) float out_s[2][2][4][64];
    __shared__ __align__(8) u64 mbar[2][2][8];
    __shared__ u64 As2[8][128];
    __shared__ u64 Bs2[8][128];
    __shared__ int s_job;

    const int cl = blockIdx.x >> 3;
    const int r  = blockIdx.x & 7;

    if (cl >= 16) {
        worker_loop(ys1, Wih2, bi2, bh2, xp2, As2, Bs2, &s_job);
        return;
    }

    if (cl < 8) {
        // layer-1 recurrence: xp1 fully ready, publish prog for B gating
        rnn_run<0, true, true>(xp1, Whh1, ys1, cl * 8, r, cl * 8 + r,
                               h_s, redv, out_s, mbar,
                               nullptr, nullptr, nullptr, nullptr, nullptr,
                               As2, Bs2, &s_job);
        worker_loop(ys1, Wih2, bi2, bh2, xp2, As2, Bs2, &s_job);
        return;
    }

    // layer-2 recurrence: gated on g_dB (xp2 blocks); helps B while blocked
    rnn_run<2, false, false>(xp2, Whh2, ys2, (cl - 8) * 8, r, 0,
                             h_s, redv, out_s, mbar,
                             ys1, Wih2, bi2, bh2, xp2,
                             As2, Bs2, &s_job);
}

// =======================================================================
__global__ void reset_counters() {
    const int i = threadIdx.x;
    if (i == 0) { g_jcA = 0; g_jcB = 0; }
    if (i < 4) { g_dA[i] = 0; g_dB[i] = 0; }
    if (i < 64) g_prog[i] = 0;
}

// =======================================================================
__global__ void proj_kernel(const float* __restrict__ ys,
                            const float* __restrict__ Wout,
                            const float* __restrict__ bout,
                            float* __restrict__ out)
{
    const int b    = blockIdx.x;
    const int c    = threadIdx.y;
    const int lane = threadIdx.x;
    const float* hrow = &ys[((size_t)b * TT + (TT - 1)) * HH];
    const float* wrow = &Wout[(size_t)c * HH];
    float s = 0.f;
    for (int k = lane; k < HH; k += 32) s += hrow[k] * wrow[k];
    #pragma unroll
    for (int o = 16; o > 0; o >>= 1) s += __shfl_down_sync(0xffffffffu, s, o);
    if (lane == 0) out[b * NCLS + c] = s + bout[c];
}

// =======================================================================
extern "C" void kernel_launch(void* const* d_in, const int* in_sizes, int n_in,
                              void* d_out, int out_size)
{
    (void)in_sizes; (void)n_in; (void)out_size;
    const float* x    = (const float*)d_in[0];
    const float* Wih[3] = {(const float*)d_in[1], (const float*)d_in[5], (const float*)d_in[9]};
    const float* Whh[3] = {(const float*)d_in[2], (const float*)d_in[6], (const float*)d_in[10]};
    const float* bih[3] = {(const float*)d_in[3], (const float*)d_in[7], (const float*)d_in[11]};
    const float* bhh[3] = {(const float*)d_in[4], (const float*)d_in[8], (const float*)d_in[12]};
    const float* Wout = (const float*)d_in[13];
    const float* bout = (const float*)d_in[14];
    float* out = (float*)d_out;

    float *xp0, *xp1, *xp2, *ys0, *ys1, *ys2;
    cudaGetSymbolAddress((void**)&xp0, g_xp0);
    cudaGetSymbolAddress((void**)&xp1, g_xp1);
    cudaGetSymbolAddress((void**)&xp2, g_xp2);
    cudaGetSymbolAddress((void**)&ys0, g_ys0);
    cudaGetSymbolAddress((void**)&ys1, g_ys1);
    cudaGetSymbolAddress((void**)&ys2, g_ys2);

    // Launch 1 (R9): A (xp0 from x) + rnn layer0 + B workers (xp1 from ys0)
    reset_counters<<<1, 64>>>();
    megaL0<<<144, 256>>>(x, Wih[0], bih[0], bhh[0],
                         Whh[0],
                         Wih[1], bih[1], bhh[1],
                         xp0, xp1, ys0);

    // Launch 2: rnn layer1 + B (xp2 from ys1) + rnn layer2 (gated, helping)
    reset_counters<<<1, 64>>>();
    megaL12<<<144, 256>>>(xp1, Whh[1], ys1,
                          Wih[2], bih[2], bhh[2], xp2,
                          Whh[2], ys2);

    proj_kernel<<<64, dim3(32, 5)>>>(ys2, Wout, bout, out);
}